// round 16
// baseline (speedup 1.0000x reference)
#include <cuda_runtime.h>
#include <cuda_fp16.h>
#include <cstdint>
#include <math.h>

#define Tn 4096
#define Dn 1024
#define Hn 4096
#define En 8
#define NSn 2
#define NEn (En + NSn)
#define ROUTED_ROWS (2 * Tn)
#define ALLROWS (ROUTED_ROWS + NSn * Tn)

// ---- static scratch (no allocation APIs); aligned for cp.async 16B ----
__device__ __align__(1024) __half g_Xe[(size_t)Tn * Dn];          // x fp16 [t][D]
// Shared weight buffer: W1^T fp16 [z][H][D] during FFN1, then W2^T fp16 [z][D][H].
__device__ __align__(1024) __half g_We[(size_t)NEn * Hn * Dn];
__device__ __align__(1024) __half g_He[(size_t)ALLROWS * Hn];     // hidden fp16
__device__ int g_cnt[En];
__device__ int g_list[En * Tn];

// ---------------- PTX helpers (non-'a' features only) ----------------
__device__ __forceinline__ uint32_t smem_u32(const void* p) {
    uint32_t a;
    asm("{ .reg .u64 t; cvta.to.shared.u64 t, %1; cvt.u32.u64 %0, t; }" : "=r"(a) : "l"(p));
    return a;
}
__device__ __forceinline__ void cp16(uint32_t s, const void* g) {
    asm volatile("cp.async.cg.shared.global [%0], [%1], 16;" :: "r"(s), "l"(g));
}
__device__ __forceinline__ void ldsm4(uint32_t* r, uint32_t a) {
    asm volatile("ldmatrix.sync.aligned.m8n8.x4.shared.b16 {%0,%1,%2,%3}, [%4];"
                 : "=r"(r[0]), "=r"(r[1]), "=r"(r[2]), "=r"(r[3]) : "r"(a));
}
__device__ __forceinline__ void mma16816(float* d, const uint32_t* a, uint32_t b0, uint32_t b1) {
    asm volatile(
        "mma.sync.aligned.m16n8k16.row.col.f32.f16.f16.f32 "
        "{%0,%1,%2,%3}, {%4,%5,%6,%7}, {%8,%9}, {%0,%1,%2,%3};"
        : "+f"(d[0]), "+f"(d[1]), "+f"(d[2]), "+f"(d[3])
        : "r"(a[0]), "r"(a[1]), "r"(a[2]), "r"(a[3]), "r"(b0), "r"(b1));
}
__device__ __forceinline__ float gelu_f(float v) {
    float u = 0.7978845608028654f * (v + 0.044715f * v * v * v);
    float t;
    asm("tanh.approx.f32 %0, %1;" : "=f"(t) : "f"(u));
    return 0.5f * v * (1.0f + t);
}

// ---------------- x conversion (+ count zeroing; runs BEFORE router) ----------------
__global__ void ext_x_kernel(const float* __restrict__ x) {
    if (blockIdx.x == 0 && threadIdx.x < En) g_cnt[threadIdx.x] = 0;
    int idx = blockIdx.x * 256 + threadIdx.x;   // one float4 per thread
    if (idx * 4 >= Tn * Dn) return;
    float4 v = *(const float4*)(x + idx * 4);
    __half2 a = __floats2half2_rn(v.x, v.y);
    __half2 b = __floats2half2_rn(v.z, v.w);
    *(uint2*)(g_Xe + idx * 4) = make_uint2(*(uint32_t*)&a, *(uint32_t*)&b);
}

// ---------------- router ----------------
__global__ void router_kernel(const float* __restrict__ x,
                              const float* __restrict__ Wr,
                              const float* __restrict__ br,
                              const float* __restrict__ gum) {
    int t = blockIdx.x;
    int tid = threadIdx.x;  // 128
    const float* xr = x + (size_t)t * Dn;
    float acc[En];
#pragma unroll
    for (int e = 0; e < En; e++) acc[e] = 0.f;
    for (int d = tid; d < Dn; d += 128) {
        float xv = xr[d];
        float4 w0 = *(const float4*)(Wr + d * En);
        float4 w1 = *(const float4*)(Wr + d * En + 4);
        acc[0] += xv * w0.x; acc[1] += xv * w0.y;
        acc[2] += xv * w0.z; acc[3] += xv * w0.w;
        acc[4] += xv * w1.x; acc[5] += xv * w1.y;
        acc[6] += xv * w1.z; acc[7] += xv * w1.w;
    }
#pragma unroll
    for (int e = 0; e < En; e++) {
#pragma unroll
        for (int off = 16; off; off >>= 1)
            acc[e] += __shfl_down_sync(0xffffffffu, acc[e], off);
    }
    __shared__ float red[4][En];
    if ((tid & 31) == 0) {
#pragma unroll
        for (int e = 0; e < En; e++) red[tid >> 5][e] = acc[e];
    }
    __syncthreads();
    if (tid == 0) {
        float s[En];
#pragma unroll
        for (int e = 0; e < En; e++)
            s[e] = red[0][e] + red[1][e] + red[2][e] + red[3][e]
                 + br[e] + gum[(size_t)t * En + e];
        int i1 = 0;
#pragma unroll
        for (int e = 1; e < En; e++) if (s[e] > s[i1]) i1 = e;
        int i2 = (i1 == 0) ? 1 : 0;
#pragma unroll
        for (int e = 0; e < En; e++)
            if (e != i1 && s[e] > s[i2]) i2 = e;
        int p1 = atomicAdd(&g_cnt[i1], 1); g_list[i1 * Tn + p1] = t;
        int p2 = atomicAdd(&g_cnt[i2], 1); g_list[i2 * Tn + p2] = t;
    }
}

// ---------------- weight conversion: routed + shared in ONE launch ----------------
template <int SK, int SN>
__global__ void ext_w_all(const float* __restrict__ Wr_, const float* __restrict__ Ws_) {
    __shared__ float tile[32][33];
    int z = blockIdx.z;
    int n0 = blockIdx.x * 32, k0 = blockIdx.y * 32;
    const float* Wz = (z < En) ? Wr_ + (size_t)z * SK * SN
                               : Ws_ + (size_t)(z - En) * SK * SN;
    __half* dst = g_We + (size_t)z * SN * (size_t)SK;
    int tx = threadIdx.x, ty = threadIdx.y;
#pragma unroll
    for (int r = 0; r < 32; r += 8)
        tile[ty + r][tx] = Wz[(size_t)(k0 + ty + r) * SN + n0 + tx];
    __syncthreads();
#pragma unroll
    for (int r = 0; r < 32; r += 8)
        dst[(size_t)(n0 + ty + r) * SK + (k0 + tx)] = __float2half_rn(tile[tx][ty + r]);
}

// ---------------- mma.sync fp16 GEMM: BM=BN=128, warp tile 32x64, BK=64, 3-stage ----------------
#define BM 128
#define BN 128
#define BK 64
#define STAGES 3
#define ROWPB 144                     // pitch bytes: 128 data + 16 pad (stride 9 mod 8 = 1)
#define TILEB (128 * ROWPB)           // 18432 B per operand tile
#define STGB (2 * TILEB)              // 36864 B per stage
#define SMEMT (STAGES * STGB)         // 110592 B

// One launch covers routed (z<En, gathered) + shared (z>=En, dense) experts.
// IS1: He[row] = fp16(gelu(X@W1+b1));  !IS1: out[tok] += H@W2+b2
template <int KD, int NT, bool IS1>
__global__ void __launch_bounds__(256, 2)
moe_gemm(const float* __restrict__ biasR, const float* __restrict__ biasS,
         float* __restrict__ outF) {
    int z = blockIdx.z;
    bool gather = z < En;
    int M;
    size_t rowBase;
    if (gather) {
        M = g_cnt[z];
        int off = 0;
#pragma unroll
        for (int e = 0; e < En; e++) off += (e < z) ? g_cnt[e] : 0;
        rowBase = (size_t)off;
    } else {
        M = Tn;
        rowBase = ROUTED_ROWS + (size_t)(z - En) * Tn;
    }
    int m0 = blockIdx.y * BM;
    if (m0 >= M) return;
    int n0 = blockIdx.x * BN;
    int tid = threadIdx.x, lane = tid & 31, wid = tid >> 5;
    int wm = wid & 3, wn = wid >> 2;     // 4 x 2 warp grid; warp tile 32m x 64n

    extern __shared__ __align__(1024) char smem[];
    uint32_t sb = smem_u32(smem);

    // Loader: row = tid>>1, 64B half = (tid&1); 4 cp16 per operand per stage
    int arow = m0 + (tid >> 1);
    int rr = (arow < M) ? arow : (M - 1);
    const __half* aRow;
    if (IS1) {
        int tok = gather ? g_list[z * Tn + rr] : rr;
        aRow = g_Xe + (size_t)tok * KD;
    } else {
        aRow = g_He + (rowBase + rr) * (size_t)KD;
    }
    const __half* bRowW = g_We + ((size_t)z * NT + n0 + (tid >> 1)) * (size_t)KD;

    const int nIter = KD / BK;
    uint32_t stBase = sb + (tid >> 1) * ROWPB + (tid & 1) * 64;
    // strength-reduced sequential load pointers
    const __half* aP = aRow + (tid & 1) * 32;
    const __half* bP = bRowW + (tid & 1) * 32;

    float d[2][8][4];
#pragma unroll
    for (int a = 0; a < 2; a++)
#pragma unroll
        for (int b = 0; b < 8; b++)
#pragma unroll
            for (int c = 0; c < 4; c++) d[a][b][c] = 0.f;

    auto loadStage = [&](int s) {
        uint32_t sa = stBase + s * STGB;
        cp16(sa,      aP);
        cp16(sa + 16, aP + 8);
        cp16(sa + 32, aP + 16);
        cp16(sa + 48, aP + 24);
        uint32_t sB = sa + TILEB;
        cp16(sB,      bP);
        cp16(sB + 16, bP + 8);
        cp16(sB + 32, bP + 16);
        cp16(sB + 48, bP + 24);
        aP += BK;
        bP += BK;
    };

    loadStage(0);
    asm volatile("cp.async.commit_group;" ::: "memory");
    loadStage(1);
    asm volatile("cp.async.commit_group;" ::: "memory");

    // hoisted ldmatrix base addresses
    int lrow = lane & 15, lcol = (lane >> 4) * 16;
    uint32_t aAddr = sb + (wm * 32 + lrow) * ROWPB + lcol;
    uint32_t bAddr = sb + TILEB + (wn * 64 + lrow) * ROWPB + lcol;

    for (int j = 0; j < nIter; j++) {
        int s = j % STAGES;
        asm volatile("cp.async.wait_group 1;" ::: "memory");
        __syncthreads();
        if (j + 2 < nIter) loadStage((j + 2) % STAGES);
        asm volatile("cp.async.commit_group;" ::: "memory");

        uint32_t As = aAddr + s * STGB;
        uint32_t Bs = bAddr + s * STGB;
#pragma unroll
        for (int k16 = 0; k16 < 4; k16++) {
            uint32_t af[2][4];
#pragma unroll
            for (int mi = 0; mi < 2; mi++)
                ldsm4(af[mi], As + mi * (16 * ROWPB) + k16 * 32);
            uint32_t bf[4][4];
#pragma unroll
            for (int g = 0; g < 4; g++)
                ldsm4(bf[g], Bs + g * (16 * ROWPB) + k16 * 32);
#pragma unroll
            for (int mi = 0; mi < 2; mi++)
#pragma unroll
                for (int t = 0; t < 8; t++) {
                    int g = t >> 1, w = t & 1;
                    mma16816(d[mi][t], af[mi], bf[g][w], bf[g][2 + w]);
                }
        }
    }

    // ---- epilogue ----
    const float* bz = gather ? (biasR + (size_t)z * NT) : (biasS + (size_t)(z - En) * NT);
    int cb = n0 + wn * 64 + (lane & 3) * 2;
    int r0 = m0 + wm * 32 + (lane >> 2);
#pragma unroll
    for (int mi = 0; mi < 2; mi++) {
#pragma unroll
        for (int half = 0; half < 2; half++) {   // regs {0,1} row r, {2,3} row r+8
            int row = r0 + mi * 16 + half * 8;
            if (row >= M) continue;
            if (IS1) {
                __half* dstH = g_He + (rowBase + row) * (size_t)NT;
#pragma unroll
                for (int ni = 0; ni < 8; ni++) {
                    int col = cb + ni * 8;
                    float v0 = gelu_f(d[mi][ni][half * 2 + 0] + bz[col]);
                    float v1 = gelu_f(d[mi][ni][half * 2 + 1] + bz[col + 1]);
                    __half2 p = __floats2half2_rn(v0, v1);
                    *(uint32_t*)(dstH + col) = *(uint32_t*)&p;
                }
            } else {
                int g = gather ? g_list[z * Tn + row] : row;
                float* od = outF + (size_t)g * Dn;
#pragma unroll
                for (int ni = 0; ni < 8; ni++) {
                    int col = cb + ni * 8;
                    atomicAdd(&od[col],     d[mi][ni][half * 2 + 0] + bz[col]);
                    atomicAdd(&od[col + 1], d[mi][ni][half * 2 + 1] + bz[col + 1]);
                }
            }
        }
    }
}

extern "C" void kernel_launch(void* const* d_in, const int* in_sizes, int n_in,
                              void* d_out, int out_size) {
    const float* x   = (const float*)d_in[0];
    const float* Ws1 = (const float*)d_in[1];
    const float* bs1 = (const float*)d_in[2];
    const float* Ws2 = (const float*)d_in[3];
    const float* bs2 = (const float*)d_in[4];
    const float* We1 = (const float*)d_in[5];
    const float* be1 = (const float*)d_in[6];
    const float* We2 = (const float*)d_in[7];
    const float* be2 = (const float*)d_in[8];
    const float* Wr  = (const float*)d_in[9];
    const float* br  = (const float*)d_in[10];
    const float* gum = (const float*)d_in[11];
    float* out = (float*)d_out;

    cudaFuncSetAttribute(moe_gemm<Dn, Hn, true >, cudaFuncAttributeMaxDynamicSharedMemorySize, SMEMT);
    cudaFuncSetAttribute(moe_gemm<Hn, Dn, false>, cudaFuncAttributeMaxDynamicSharedMemorySize, SMEMT);

    dim3 bw(32, 8);
    // Launch slots (for ncu -s 5 -c 1): 1 memset, 2 ext_x, 3 router, 4 ext_w, 5 GEMM1.
    cudaMemsetAsync(out, 0, (size_t)out_size * sizeof(float), 0);
    ext_x_kernel<<<(Tn * Dn) / 1024, 256>>>(x);                  // also zeroes g_cnt
    router_kernel<<<Tn, 128>>>(x, Wr, br, gum);

    // Phase 1: W1^T (routed+shared) into g_We, then FFN1 for all 10 experts.
    ext_w_all<Dn, Hn><<<dim3(Hn / 32, Dn / 32, NEn), bw>>>(We1, Ws1);
    moe_gemm<Dn, Hn, true ><<<dim3(Hn / BN, Tn / BM, NEn), 256, SMEMT>>>(be1, bs1, nullptr);

    // Phase 2: W2^T overwrites g_We (stream-ordered after FFN1), then FFN2.
    ext_w_all<Hn, Dn><<<dim3(Dn / 32, Hn / 32, NEn), bw>>>(We2, Ws2);
    moe_gemm<Hn, Dn, false><<<dim3(Dn / BN, Tn / BM, NEn), 256, SMEMT>>>(be2, bs2, out);
}

// round 17
// speedup vs baseline: 1.2492x; 1.2492x over previous
#include <cuda_runtime.h>
#include <cuda_fp16.h>
#include <cstdint>
#include <math.h>

#define Tn 4096
#define Dn 1024
#define Hn 4096
#define En 8
#define NSn 2
#define NEn (En + NSn)
#define ROUTED_ROWS (2 * Tn)
#define ALLROWS (ROUTED_ROWS + NSn * Tn)

// ---- static scratch (no allocation APIs); aligned for cp.async 16B ----
__device__ __align__(1024) __half g_Xe[(size_t)Tn * Dn];          // x fp16 [t][D]
// Shared weight buffer: W1^T fp16 [z][H][D] during FFN1, then W2^T fp16 [z][D][H].
__device__ __align__(1024) __half g_We[(size_t)NEn * Hn * Dn];
__device__ __align__(1024) __half g_He[(size_t)ALLROWS * Hn];     // hidden fp16
__device__ int g_cnt[En];
__device__ int g_list[En * Tn];

// ---------------- PTX helpers (non-'a' features only) ----------------
__device__ __forceinline__ uint32_t smem_u32(const void* p) {
    uint32_t a;
    asm("{ .reg .u64 t; cvta.to.shared.u64 t, %1; cvt.u32.u64 %0, t; }" : "=r"(a) : "l"(p));
    return a;
}
__device__ __forceinline__ void cp16(uint32_t s, const void* g) {
    asm volatile("cp.async.cg.shared.global [%0], [%1], 16;" :: "r"(s), "l"(g));
}
__device__ __forceinline__ void ldsm4(uint32_t* r, uint32_t a) {
    asm volatile("ldmatrix.sync.aligned.m8n8.x4.shared.b16 {%0,%1,%2,%3}, [%4];"
                 : "=r"(r[0]), "=r"(r[1]), "=r"(r[2]), "=r"(r[3]) : "r"(a));
}
__device__ __forceinline__ void mma16816(float* d, const uint32_t* a, uint32_t b0, uint32_t b1) {
    asm volatile(
        "mma.sync.aligned.m16n8k16.row.col.f32.f16.f16.f32 "
        "{%0,%1,%2,%3}, {%4,%5,%6,%7}, {%8,%9}, {%0,%1,%2,%3};"
        : "+f"(d[0]), "+f"(d[1]), "+f"(d[2]), "+f"(d[3])
        : "r"(a[0]), "r"(a[1]), "r"(a[2]), "r"(a[3]), "r"(b0), "r"(b1));
}
__device__ __forceinline__ float gelu_f(float v) {
    float u = 0.7978845608028654f * (v + 0.044715f * v * v * v);
    float t;
    asm("tanh.approx.f32 %0, %1;" : "=f"(t) : "f"(u));
    return 0.5f * v * (1.0f + t);
}

// ---------------- x conversion (+ count zeroing; runs BEFORE router) ----------------
__global__ void ext_x_kernel(const float* __restrict__ x) {
    if (blockIdx.x == 0 && threadIdx.x < En) g_cnt[threadIdx.x] = 0;
    int idx = blockIdx.x * 256 + threadIdx.x;   // one float4 per thread
    if (idx * 4 >= Tn * Dn) return;
    float4 v = *(const float4*)(x + idx * 4);
    __half2 a = __floats2half2_rn(v.x, v.y);
    __half2 b = __floats2half2_rn(v.z, v.w);
    *(uint2*)(g_Xe + idx * 4) = make_uint2(*(uint32_t*)&a, *(uint32_t*)&b);
}

// ---------------- router ----------------
__global__ void router_kernel(const float* __restrict__ x,
                              const float* __restrict__ Wr,
                              const float* __restrict__ br,
                              const float* __restrict__ gum) {
    int t = blockIdx.x;
    int tid = threadIdx.x;  // 128
    const float* xr = x + (size_t)t * Dn;
    float acc[En];
#pragma unroll
    for (int e = 0; e < En; e++) acc[e] = 0.f;
    for (int d = tid; d < Dn; d += 128) {
        float xv = xr[d];
        float4 w0 = *(const float4*)(Wr + d * En);
        float4 w1 = *(const float4*)(Wr + d * En + 4);
        acc[0] += xv * w0.x; acc[1] += xv * w0.y;
        acc[2] += xv * w0.z; acc[3] += xv * w0.w;
        acc[4] += xv * w1.x; acc[5] += xv * w1.y;
        acc[6] += xv * w1.z; acc[7] += xv * w1.w;
    }
#pragma unroll
    for (int e = 0; e < En; e++) {
#pragma unroll
        for (int off = 16; off; off >>= 1)
            acc[e] += __shfl_down_sync(0xffffffffu, acc[e], off);
    }
    __shared__ float red[4][En];
    if ((tid & 31) == 0) {
#pragma unroll
        for (int e = 0; e < En; e++) red[tid >> 5][e] = acc[e];
    }
    __syncthreads();
    if (tid == 0) {
        float s[En];
#pragma unroll
        for (int e = 0; e < En; e++)
            s[e] = red[0][e] + red[1][e] + red[2][e] + red[3][e]
                 + br[e] + gum[(size_t)t * En + e];
        int i1 = 0;
#pragma unroll
        for (int e = 1; e < En; e++) if (s[e] > s[i1]) i1 = e;
        int i2 = (i1 == 0) ? 1 : 0;
#pragma unroll
        for (int e = 0; e < En; e++)
            if (e != i1 && s[e] > s[i2]) i2 = e;
        int p1 = atomicAdd(&g_cnt[i1], 1); g_list[i1 * Tn + p1] = t;
        int p2 = atomicAdd(&g_cnt[i2], 1); g_list[i2 * Tn + p2] = t;
    }
}

// ---------------- weight conversion: vectorized transpose, half2 stores ----------------
// src [z][SK][SN] fp32 -> g_We [z][SN][SK] fp16.  Tile: 64 k-rows x 32 n-cols.
// Block 256 threads. Load: rows coalesced 32 floats (128B). Store: each warp writes
// one n-row's 64 k-halves as 32 half2 (128B full-efficiency).
template <int SK, int SN>
__global__ void ext_w_all(const float* __restrict__ Wr_, const float* __restrict__ Ws_) {
    __shared__ float tile[64][33];
    int z = blockIdx.z;
    int n0 = blockIdx.x * 32, k0 = blockIdx.y * 64;
    const float* Wz = (z < En) ? Wr_ + (size_t)z * SK * SN
                               : Ws_ + (size_t)(z - En) * SK * SN;
    __half* dst = g_We + (size_t)z * SN * (size_t)SK;
    int tid = threadIdx.x;
    int ltx = tid & 31, lty = tid >> 5;   // 32 x 8
    // load 64 rows x 32 cols; each thread 8 rows
#pragma unroll
    for (int r = 0; r < 64; r += 8)
        tile[r + lty][ltx] = Wz[(size_t)(k0 + r + lty) * SN + n0 + ltx];
    __syncthreads();
    // store: warp w handles n-rows {w, w+8, w+16, w+24}; lane l -> k pair 2l
#pragma unroll
    for (int nr = 0; nr < 32; nr += 8) {
        int n = nr + lty;
        __half2 p = __floats2half2_rn(tile[2 * ltx][n], tile[2 * ltx + 1][n]);
        *(__half2*)(dst + (size_t)(n0 + n) * SK + k0 + 2 * ltx) = p;
    }
}

// ---------------- mma.sync fp16 GEMM: BM=BN=128, warp tile 32x64, BK=32, 3-stage ----------------
#define BM 128
#define BN 128
#define BK 32
#define STAGES 3
#define ROWPB 80                      // padded row pitch in bytes (40 halves)
#define TILEB (128 * ROWPB)           // 10240 B per operand tile
#define STGB (2 * TILEB)              // 20480 B per stage
#define SMEMT (STAGES * STGB)         // 61440 B

// One launch covers routed (z<En, gathered) + shared (z>=En, dense) experts.
// IS1: He[row] = fp16(gelu(X@W1+b1));  !IS1: out[tok] += H@W2+b2
template <int KD, int NT, bool IS1>
__global__ void __launch_bounds__(256, 2)
moe_gemm(const float* __restrict__ biasR, const float* __restrict__ biasS,
         float* __restrict__ outF) {
    int z = blockIdx.z;
    bool gather = z < En;
    int M;
    size_t rowBase;
    if (gather) {
        M = g_cnt[z];
        int off = 0;
#pragma unroll
        for (int e = 0; e < En; e++) off += (e < z) ? g_cnt[e] : 0;
        rowBase = (size_t)off;
    } else {
        M = Tn;
        rowBase = ROUTED_ROWS + (size_t)(z - En) * Tn;
    }
    int m0 = blockIdx.y * BM;
    if (m0 >= M) return;
    int n0 = blockIdx.x * BN;
    int tid = threadIdx.x, lane = tid & 31, wid = tid >> 5;
    int wm = wid & 3, wn = wid >> 2;     // 4 x 2 warp grid; warp tile 32m x 64n

    extern __shared__ __align__(1024) char smem[];
    uint32_t sb = smem_u32(smem);

    // A loader: row = tid>>1, 32B chunk = (tid&1)
    int arow = m0 + (tid >> 1);
    int rr = (arow < M) ? arow : (M - 1);
    const __half* aRow;
    if (IS1) {
        int tok = gather ? g_list[z * Tn + rr] : rr;
        aRow = g_Xe + (size_t)tok * KD;
    } else {
        aRow = g_He + (rowBase + rr) * (size_t)KD;
    }
    const __half* bRowW = g_We + ((size_t)z * NT + n0 + (tid >> 1)) * (size_t)KD;

    const int nIter = KD / BK;
    uint32_t stBase = sb + (tid >> 1) * ROWPB + (tid & 1) * 32;
    // strength-reduced sequential load pointers
    const __half* aP = aRow + (tid & 1) * 16;
    const __half* bP = bRowW + (tid & 1) * 16;

    float d[2][8][4];
#pragma unroll
    for (int a = 0; a < 2; a++)
#pragma unroll
        for (int b = 0; b < 8; b++)
#pragma unroll
            for (int c = 0; c < 4; c++) d[a][b][c] = 0.f;

    auto loadStage = [&](int s) {
        uint32_t sa = stBase + s * STGB;
        cp16(sa,      aP);
        cp16(sa + 16, aP + 8);
        uint32_t sB = sa + TILEB;
        cp16(sB,      bP);
        cp16(sB + 16, bP + 8);
        aP += BK;
        bP += BK;
    };

    loadStage(0);
    asm volatile("cp.async.commit_group;" ::: "memory");
    loadStage(1);
    asm volatile("cp.async.commit_group;" ::: "memory");

    // hoisted ldmatrix base addresses (loop adds only s*STGB + small consts)
    int lrow = lane & 15, lcol = (lane >> 4) * 16;
    uint32_t aAddr = sb + (wm * 32 + lrow) * ROWPB + lcol;
    uint32_t bAddr = sb + TILEB + (wn * 64 + lrow) * ROWPB + lcol;

    for (int j = 0; j < nIter; j++) {
        int s = j % STAGES;
        asm volatile("cp.async.wait_group 1;" ::: "memory");
        __syncthreads();
        if (j + 2 < nIter) loadStage((j + 2) % STAGES);
        asm volatile("cp.async.commit_group;" ::: "memory");

        uint32_t As = aAddr + s * STGB;
        uint32_t Bs = bAddr + s * STGB;
#pragma unroll
        for (int k16 = 0; k16 < 2; k16++) {
            uint32_t af[2][4];
#pragma unroll
            for (int mi = 0; mi < 2; mi++)
                ldsm4(af[mi], As + mi * (16 * ROWPB) + k16 * 32);
            uint32_t bf[4][4];
#pragma unroll
            for (int g = 0; g < 4; g++)
                ldsm4(bf[g], Bs + g * (16 * ROWPB) + k16 * 32);
#pragma unroll
            for (int mi = 0; mi < 2; mi++)
#pragma unroll
                for (int t = 0; t < 8; t++) {
                    int g = t >> 1, w = t & 1;
                    mma16816(d[mi][t], af[mi], bf[g][w], bf[g][2 + w]);
                }
        }
    }

    // ---- epilogue ----
    const float* bz = gather ? (biasR + (size_t)z * NT) : (biasS + (size_t)(z - En) * NT);
    int cb = n0 + wn * 64 + (lane & 3) * 2;
    int r0 = m0 + wm * 32 + (lane >> 2);
#pragma unroll
    for (int mi = 0; mi < 2; mi++) {
#pragma unroll
        for (int half = 0; half < 2; half++) {   // regs {0,1} row r, {2,3} row r+8
            int row = r0 + mi * 16 + half * 8;
            if (row >= M) continue;
            if (IS1) {
                __half* dstH = g_He + (rowBase + row) * (size_t)NT;
#pragma unroll
                for (int ni = 0; ni < 8; ni++) {
                    int col = cb + ni * 8;
                    float v0 = gelu_f(d[mi][ni][half * 2 + 0] + bz[col]);
                    float v1 = gelu_f(d[mi][ni][half * 2 + 1] + bz[col + 1]);
                    __half2 p = __floats2half2_rn(v0, v1);
                    *(uint32_t*)(dstH + col) = *(uint32_t*)&p;
                }
            } else {
                int g = gather ? g_list[z * Tn + row] : row;
                float* od = outF + (size_t)g * Dn;
#pragma unroll
                for (int ni = 0; ni < 8; ni++) {
                    int col = cb + ni * 8;
                    atomicAdd(&od[col],     d[mi][ni][half * 2 + 0] + bz[col]);
                    atomicAdd(&od[col + 1], d[mi][ni][half * 2 + 1] + bz[col + 1]);
                }
            }
        }
    }
}

extern "C" void kernel_launch(void* const* d_in, const int* in_sizes, int n_in,
                              void* d_out, int out_size) {
    const float* x   = (const float*)d_in[0];
    const float* Ws1 = (const float*)d_in[1];
    const float* bs1 = (const float*)d_in[2];
    const float* Ws2 = (const float*)d_in[3];
    const float* bs2 = (const float*)d_in[4];
    const float* We1 = (const float*)d_in[5];
    const float* be1 = (const float*)d_in[6];
    const float* We2 = (const float*)d_in[7];
    const float* be2 = (const float*)d_in[8];
    const float* Wr  = (const float*)d_in[9];
    const float* br  = (const float*)d_in[10];
    const float* gum = (const float*)d_in[11];
    float* out = (float*)d_out;

    cudaFuncSetAttribute(moe_gemm<Dn, Hn, true >, cudaFuncAttributeMaxDynamicSharedMemorySize, SMEMT);
    cudaFuncSetAttribute(moe_gemm<Hn, Dn, false>, cudaFuncAttributeMaxDynamicSharedMemorySize, SMEMT);

    // Launch slots (for ncu -s 5 -c 1): 1 memset, 2 ext_x, 3 router, 4 ext_w, 5 GEMM1.
    cudaMemsetAsync(out, 0, (size_t)out_size * sizeof(float), 0);
    ext_x_kernel<<<(Tn * Dn) / 1024, 256>>>(x);                  // also zeroes g_cnt
    router_kernel<<<Tn, 128>>>(x, Wr, br, gum);

    // Phase 1: W1^T (routed+shared) into g_We, then FFN1 for all 10 experts.
    ext_w_all<Dn, Hn><<<dim3(Hn / 32, Dn / 64, NEn), 256>>>(We1, Ws1);
    moe_gemm<Dn, Hn, true ><<<dim3(Hn / BN, Tn / BM, NEn), 256, SMEMT>>>(be1, bs1, nullptr);

    // Phase 2: W2^T overwrites g_We (stream-ordered after FFN1), then FFN2.
    ext_w_all<Hn, Dn><<<dim3(Dn / 32, Hn / 64, NEn), 256>>>(We2, Ws2);
    moe_gemm<Hn, Dn, false><<<dim3(Dn / BN, Tn / BM, NEn), 256, SMEMT>>>(be2, bs2, out);
}